// round 1
// baseline (speedup 1.0000x reference)
#include <cuda_runtime.h>

// Problem constants
namespace {
constexpr int B_ = 32, S_ = 500, C_ = 1024, H_ = 16, D_ = 64;
constexpr int BH_ = B_ * H_;   // 512
constexpr int M_  = B_ * S_;   // 16000
}

// Scratch (allocation-free rule: __device__ globals)
__device__ float g_q[BH_ * S_ * D_];
__device__ float g_k[BH_ * S_ * D_];
__device__ float g_v[BH_ * S_ * D_];
__device__ float g_y[M_ * C_];

// ---------------------------------------------------------------------------
// 128x128 tiled fp32 GEMM, BK=8, 256 threads, 8x8 micro-tile, reg prefetch.
// A: row-major [M x 1024], W: row-major [1024 x 1024]. M,N multiples of 128.
// ---------------------------------------------------------------------------
__device__ __forceinline__ void gemm_body(
    const float* __restrict__ A, const float* __restrict__ W,
    int m0, int n0, float acc[8][8],
    float (*sA)[128], float (*sB)[128])
{
    const int tid = threadIdx.x;
    const int ty = tid >> 4, tx = tid & 15;

    const int aRow = tid >> 1;            // 0..127
    const int aK   = (tid & 1) << 2;      // 0 or 4
    const int bK   = tid >> 5;            // 0..7
    const int bCol = (tid & 31) << 2;     // 0..124

    const float* Ap = A + (m0 + aRow) * C_ + aK;
    const float* Bp = W + bK * C_ + n0 + bCol;

    float4 ra = *(const float4*)Ap;
    float4 rb = *(const float4*)Bp;

#pragma unroll
    for (int i = 0; i < 8; i++)
#pragma unroll
        for (int j = 0; j < 8; j++) acc[i][j] = 0.f;

    for (int k0 = 0; k0 < C_; k0 += 8) {
        __syncthreads();
        sA[aK + 0][aRow] = ra.x;
        sA[aK + 1][aRow] = ra.y;
        sA[aK + 2][aRow] = ra.z;
        sA[aK + 3][aRow] = ra.w;
        *(float4*)&sB[bK][bCol] = rb;
        __syncthreads();

        if (k0 + 8 < C_) {
            ra = *(const float4*)(Ap + k0 + 8);
            rb = *(const float4*)(Bp + (k0 + 8) * C_);
        }

#pragma unroll
        for (int kk = 0; kk < 8; kk++) {
            float4 a0 = *(const float4*)&sA[kk][ty * 8];
            float4 a1 = *(const float4*)&sA[kk][ty * 8 + 4];
            float4 b0 = *(const float4*)&sB[kk][tx * 8];
            float4 b1 = *(const float4*)&sB[kk][tx * 8 + 4];
            float av[8] = {a0.x, a0.y, a0.z, a0.w, a1.x, a1.y, a1.z, a1.w};
            float bv[8] = {b0.x, b0.y, b0.z, b0.w, b1.x, b1.y, b1.z, b1.w};
#pragma unroll
            for (int i = 0; i < 8; i++)
#pragma unroll
                for (int j = 0; j < 8; j++)
                    acc[i][j] = fmaf(av[i], bv[j], acc[i][j]);
        }
    }
}

// QKV projections: z selects {q,k,v}; epilogue scatters to [B,H,S,D]
__global__ __launch_bounds__(256, 2) void qkv_kernel(
    const float* __restrict__ x,
    const float* __restrict__ Wq, const float* __restrict__ bq,
    const float* __restrict__ Wk, const float* __restrict__ bk,
    const float* __restrict__ Wv, const float* __restrict__ bv)
{
    __shared__ float sA[8][128];
    __shared__ float sB[8][128];

    const int which = blockIdx.z;
    const float* W    = (which == 0) ? Wq : (which == 1) ? Wk : Wv;
    const float* bias = (which == 0) ? bq : (which == 1) ? bk : bv;
    float* dst        = (which == 0) ? g_q : (which == 1) ? g_k : g_v;

    const int m0 = blockIdx.y * 128, n0 = blockIdx.x * 128;
    float acc[8][8];
    gemm_body(x, W, m0, n0, acc, sA, sB);

    const int tid = threadIdx.x;
    const int ty = tid >> 4, tx = tid & 15;
#pragma unroll
    for (int i = 0; i < 8; i++) {
        int m = m0 + ty * 8 + i;
        int b = m / S_;
        int s = m - b * S_;
#pragma unroll
        for (int j = 0; j < 8; j++) {
            int n = n0 + tx * 8 + j;
            int h = n >> 6, d = n & 63;
            dst[((b * H_ + h) * S_ + s) * D_ + d] = acc[i][j] + bias[n];
        }
    }
}

// Output projection: A = g_y [B*S, C], out row-major
__global__ __launch_bounds__(256, 2) void proj_kernel(
    const float* __restrict__ Wp, const float* __restrict__ bp,
    float* __restrict__ out)
{
    __shared__ float sA[8][128];
    __shared__ float sB[8][128];

    const int m0 = blockIdx.y * 128, n0 = blockIdx.x * 128;
    float acc[8][8];
    gemm_body(g_y, Wp, m0, n0, acc, sA, sB);

    const int tid = threadIdx.x;
    const int ty = tid >> 4, tx = tid & 15;
#pragma unroll
    for (int i = 0; i < 8; i++) {
        int m = m0 + ty * 8 + i;
#pragma unroll
        for (int j = 0; j < 8; j += 4) {
            int n = n0 + tx * 8 + j;
            float4 v = make_float4(acc[i][j + 0] + bp[n + 0],
                                   acc[i][j + 1] + bp[n + 1],
                                   acc[i][j + 2] + bp[n + 2],
                                   acc[i][j + 3] + bp[n + 3]);
            *(float4*)&out[m * C_ + n] = v;
        }
    }
}

// ---------------------------------------------------------------------------
// Flash attention: one block per (q-tile of 64, bh). 256 threads (16x16),
// each thread owns a 4x4 tile of scores / output. Online softmax.
// smem: sQ [r][d], sKP (Kt [d][c] during scores, P [r][c] during PV), sV [kk][d]
// ---------------------------------------------------------------------------
__global__ __launch_bounds__(256) void attn_kernel()
{
    constexpr int LD = 64;
    __shared__ float sQ[64 * LD];
    __shared__ float sKP[64 * LD];
    __shared__ float sV[64 * LD];

    const int qt  = blockIdx.x;   // 0..7
    const int bh  = blockIdx.y;   // 0..511
    const int tid = threadIdx.x;
    const int ty = tid >> 4, tx = tid & 15;

    const float* qb = g_q + bh * (S_ * D_);
    const float* kb = g_k + bh * (S_ * D_);
    const float* vb = g_v + bh * (S_ * D_);

    const int rL = tid >> 4;            // 0..15
    const int d4 = (tid & 15) << 2;     // 0..60

    // load Q tile (zero-pad rows >= S)
#pragma unroll
    for (int it = 0; it < 4; it++) {
        int r = rL + it * 16;
        int qpos = qt * 64 + r;
        float4 val = make_float4(0.f, 0.f, 0.f, 0.f);
        if (qpos < S_) val = *(const float4*)(qb + qpos * D_ + d4);
        *(float4*)&sQ[r * LD + d4] = val;
    }

    float o[4][4];
    float m_i[4], l_i[4];
#pragma unroll
    for (int i = 0; i < 4; i++) {
        m_i[i] = -1e30f;
        l_i[i] = 0.f;
#pragma unroll
        for (int j = 0; j < 4; j++) o[i][j] = 0.f;
    }

    for (int kt = 0; kt <= qt; kt++) {
        __syncthreads();  // previous PV done before overwriting sKP/sV

        // load K (transposed) and V tiles, zero-pad kpos >= S
#pragma unroll
        for (int it = 0; it < 4; it++) {
            int c = rL + it * 16;
            int kpos = kt * 64 + c;
            float4 kv = make_float4(0.f, 0.f, 0.f, 0.f);
            float4 vv = make_float4(0.f, 0.f, 0.f, 0.f);
            if (kpos < S_) {
                kv = *(const float4*)(kb + kpos * D_ + d4);
                vv = *(const float4*)(vb + kpos * D_ + d4);
            }
            sKP[(d4 + 0) * LD + c] = kv.x;
            sKP[(d4 + 1) * LD + c] = kv.y;
            sKP[(d4 + 2) * LD + c] = kv.z;
            sKP[(d4 + 3) * LD + c] = kv.w;
            *(float4*)&sV[c * LD + d4] = vv;
        }
        __syncthreads();

        // S = Q @ K^T  (4x4 per thread)
        float sc[4][4];
#pragma unroll
        for (int i = 0; i < 4; i++)
#pragma unroll
            for (int j = 0; j < 4; j++) sc[i][j] = 0.f;

#pragma unroll 8
        for (int dd = 0; dd < 64; dd++) {
            float4 kf = *(const float4*)&sKP[dd * LD + tx * 4];
            float q0 = sQ[(ty * 4 + 0) * LD + dd];
            float q1 = sQ[(ty * 4 + 1) * LD + dd];
            float q2 = sQ[(ty * 4 + 2) * LD + dd];
            float q3 = sQ[(ty * 4 + 3) * LD + dd];
            sc[0][0] = fmaf(q0, kf.x, sc[0][0]);
            sc[0][1] = fmaf(q0, kf.y, sc[0][1]);
            sc[0][2] = fmaf(q0, kf.z, sc[0][2]);
            sc[0][3] = fmaf(q0, kf.w, sc[0][3]);
            sc[1][0] = fmaf(q1, kf.x, sc[1][0]);
            sc[1][1] = fmaf(q1, kf.y, sc[1][1]);
            sc[1][2] = fmaf(q1, kf.z, sc[1][2]);
            sc[1][3] = fmaf(q1, kf.w, sc[1][3]);
            sc[2][0] = fmaf(q2, kf.x, sc[2][0]);
            sc[2][1] = fmaf(q2, kf.y, sc[2][1]);
            sc[2][2] = fmaf(q2, kf.z, sc[2][2]);
            sc[2][3] = fmaf(q2, kf.w, sc[2][3]);
            sc[3][0] = fmaf(q3, kf.x, sc[3][0]);
            sc[3][1] = fmaf(q3, kf.y, sc[3][1]);
            sc[3][2] = fmaf(q3, kf.z, sc[3][2]);
            sc[3][3] = fmaf(q3, kf.w, sc[3][3]);
        }

        // scale + causal / length mask
        const bool need_mask = (kt == qt) || ((kt + 1) * 64 > S_);
#pragma unroll
        for (int i = 0; i < 4; i++) {
            int qpos = qt * 64 + ty * 4 + i;
#pragma unroll
            for (int j = 0; j < 4; j++) {
                float v = sc[i][j] * 0.125f;  // 1/sqrt(64)
                if (need_mask) {
                    int kpos = kt * 64 + tx * 4 + j;
                    if (kpos > qpos || kpos >= S_) v = -1e30f;
                }
                sc[i][j] = v;
            }
        }

        // online softmax update (row stats replicated across the 16 tx lanes)
#pragma unroll
        for (int i = 0; i < 4; i++) {
            float mt = fmaxf(fmaxf(sc[i][0], sc[i][1]), fmaxf(sc[i][2], sc[i][3]));
#pragma unroll
            for (int off = 8; off > 0; off >>= 1)
                mt = fmaxf(mt, __shfl_xor_sync(0xffffffffu, mt, off));
            float mnew = fmaxf(m_i[i], mt);
            float corr = __expf(m_i[i] - mnew);
            m_i[i] = mnew;
            float rs = 0.f;
#pragma unroll
            for (int j = 0; j < 4; j++) {
                sc[i][j] = __expf(sc[i][j] - mnew);
                rs += sc[i][j];
            }
#pragma unroll
            for (int off = 8; off > 0; off >>= 1)
                rs += __shfl_xor_sync(0xffffffffu, rs, off);
            l_i[i] = l_i[i] * corr + rs;
#pragma unroll
            for (int j = 0; j < 4; j++) o[i][j] *= corr;
        }

        __syncthreads();  // all lanes done reading Kt before P overwrites it
#pragma unroll
        for (int i = 0; i < 4; i++)
            *(float4*)&sKP[(ty * 4 + i) * LD + tx * 4] =
                make_float4(sc[i][0], sc[i][1], sc[i][2], sc[i][3]);
        __syncthreads();

        // O += P @ V
#pragma unroll 8
        for (int kk = 0; kk < 64; kk++) {
            float4 vf = *(const float4*)&sV[kk * LD + tx * 4];
            float p0 = sKP[(ty * 4 + 0) * LD + kk];
            float p1 = sKP[(ty * 4 + 1) * LD + kk];
            float p2 = sKP[(ty * 4 + 2) * LD + kk];
            float p3 = sKP[(ty * 4 + 3) * LD + kk];
            o[0][0] = fmaf(p0, vf.x, o[0][0]);
            o[0][1] = fmaf(p0, vf.y, o[0][1]);
            o[0][2] = fmaf(p0, vf.z, o[0][2]);
            o[0][3] = fmaf(p0, vf.w, o[0][3]);
            o[1][0] = fmaf(p1, vf.x, o[1][0]);
            o[1][1] = fmaf(p1, vf.y, o[1][1]);
            o[1][2] = fmaf(p1, vf.z, o[1][2]);
            o[1][3] = fmaf(p1, vf.w, o[1][3]);
            o[2][0] = fmaf(p2, vf.x, o[2][0]);
            o[2][1] = fmaf(p2, vf.y, o[2][1]);
            o[2][2] = fmaf(p2, vf.z, o[2][2]);
            o[2][3] = fmaf(p2, vf.w, o[2][3]);
            o[3][0] = fmaf(p3, vf.x, o[3][0]);
            o[3][1] = fmaf(p3, vf.y, o[3][1]);
            o[3][2] = fmaf(p3, vf.z, o[3][2]);
            o[3][3] = fmaf(p3, vf.w, o[3][3]);
        }
    }

    // write y in [B, S, C] layout (so proj GEMM reads row-major)
    const int h = bh & (H_ - 1);
    const int b = bh >> 4;
#pragma unroll
    for (int i = 0; i < 4; i++) {
        int qpos = qt * 64 + ty * 4 + i;
        if (qpos >= S_) continue;
        float inv = 1.f / l_i[i];
        float4 res = make_float4(o[i][0] * inv, o[i][1] * inv,
                                 o[i][2] * inv, o[i][3] * inv);
        *(float4*)&g_y[(b * S_ + qpos) * C_ + h * D_ + tx * 4] = res;
    }
}

// ---------------------------------------------------------------------------
extern "C" void kernel_launch(void* const* d_in, const int* in_sizes, int n_in,
                              void* d_out, int out_size)
{
    const float* x  = (const float*)d_in[0];
    const float* Wq = (const float*)d_in[1];
    const float* bq = (const float*)d_in[2];
    const float* Wk = (const float*)d_in[3];
    const float* bk = (const float*)d_in[4];
    const float* Wv = (const float*)d_in[5];
    const float* bv = (const float*)d_in[6];
    const float* Wp = (const float*)d_in[7];
    const float* bp = (const float*)d_in[8];
    float* out = (float*)d_out;

    qkv_kernel<<<dim3(C_ / 128, M_ / 128, 3), 256>>>(x, Wq, bq, Wk, bk, Wv, bv);
    attn_kernel<<<dim3(8, BH_), 256>>>();
    proj_kernel<<<dim3(C_ / 128, M_ / 128), 256>>>(Wp, bp, out);
}

// round 3
// speedup vs baseline: 1.8096x; 1.8096x over previous
#include <cuda_runtime.h>
#include <cuda_bf16.h>
#include <cstdint>

namespace {
constexpr int B_ = 32, S_ = 500, C_ = 1024, H_ = 16, D_ = 64;
constexpr int BH_ = B_ * H_;   // 512
constexpr int M_  = B_ * S_;   // 16000

// GEMM smem layout: per stage [Ahi 16K][Alo 16K][Bhi 16K][Blo 16K]
constexpr int OFF_AHI = 0;
constexpr int OFF_ALO = 16384;
constexpr int OFF_BHI = 32768;
constexpr int OFF_BLO = 49152;
constexpr int STAGE   = 65536;
constexpr int NST     = 3;
constexpr int GSMEM   = STAGE * NST;   // 192KB
}

// Scratch (__device__ globals: allocation-free rule)
__device__ __align__(128) float g_q[BH_ * S_ * D_];
__device__ __align__(128) float g_k[BH_ * S_ * D_];
__device__ __align__(128) float g_v[BH_ * S_ * D_];
__device__ __align__(128) __nv_bfloat16 g_xhi[(size_t)M_ * C_];
__device__ __align__(128) __nv_bfloat16 g_xlo[(size_t)M_ * C_];
__device__ __align__(128) __nv_bfloat16 g_yhi[(size_t)M_ * C_];
__device__ __align__(128) __nv_bfloat16 g_ylo[(size_t)M_ * C_];
__device__ __align__(128) __nv_bfloat16 g_whi[4u * 1024u * 1024u];  // [z][n][k]
__device__ __align__(128) __nv_bfloat16 g_wlo[4u * 1024u * 1024u];

// ---------------------------------------------------------------------------
// helpers
// ---------------------------------------------------------------------------
static __device__ __forceinline__ uint32_t s2u(const void* p) {
    uint32_t a;
    asm("{ .reg .u64 t; cvta.to.shared.u64 t, %1; cvt.u32.u64 %0, t; }"
        : "=r"(a) : "l"(p));
    return a;
}
static __device__ __forceinline__ uint32_t swz(uint32_t o) {
    return o ^ ((o >> 3) & 0x70u);
}
static __device__ __forceinline__ void cpa16(uint32_t s, const void* g) {
    asm volatile("cp.async.cg.shared.global [%0], [%1], 16;" :: "r"(s), "l"(g));
}

#define LDSM4(r0, r1, r2, r3, a) \
    asm volatile("ldmatrix.sync.aligned.m8n8.x4.shared.b16 {%0,%1,%2,%3}, [%4];" \
                 : "=r"(r0), "=r"(r1), "=r"(r2), "=r"(r3) : "r"(a))

#define MMA_BF16(d, a, b0, b1) \
    asm volatile( \
        "mma.sync.aligned.m16n8k16.row.col.f32.bf16.bf16.f32 " \
        "{%0,%1,%2,%3}, {%4,%5,%6,%7}, {%8,%9}, {%0,%1,%2,%3};" \
        : "+f"((d)[0]), "+f"((d)[1]), "+f"((d)[2]), "+f"((d)[3]) \
        : "r"((a)[0]), "r"((a)[1]), "r"((a)[2]), "r"((a)[3]), \
          "r"(b0), "r"(b1))

// ---------------------------------------------------------------------------
// GEMM core: C[128x128] = A[128x1024] * B^T (B stored [n][k]), bf16x3 splits
// ---------------------------------------------------------------------------
static __device__ __forceinline__ void load_stage(
    uint32_t sb, int buf,
    const __nv_bfloat16* __restrict__ Ahi, const __nv_bfloat16* __restrict__ Alo,
    const __nv_bfloat16* __restrict__ Bhi, const __nv_bfloat16* __restrict__ Blo,
    int m0, int n0, int k0, int tid)
{
    const int r = tid >> 1;           // 0..127
    const int half = tid & 1;         // 0/1 -> 64B half of the 128B row
    const uint32_t base = sb + buf * STAGE;
    const size_t ga = (size_t)(m0 + r) * C_ + k0 + half * 32;
    const size_t gb = (size_t)(n0 + r) * C_ + k0 + half * 32;
#pragma unroll
    for (int i = 0; i < 4; i++) {
        uint32_t so = swz((uint32_t)(r * 128 + half * 64 + i * 16));
        cpa16(base + OFF_AHI + so, Ahi + ga + i * 8);
        cpa16(base + OFF_ALO + so, Alo + ga + i * 8);
        cpa16(base + OFF_BHI + so, Bhi + gb + i * 8);
        cpa16(base + OFF_BLO + so, Blo + gb + i * 8);
    }
}

static __device__ __forceinline__ void compute_stage(
    uint32_t base, int wm, int wn, int lane, float acc[2][8][4])
{
    const uint32_t arow  = wm * 32 + (lane & 15);
    const uint32_t acolk = (lane & 16) ? 16u : 0u;
    const uint32_t brow  = wn * 64 + (lane & 7) + ((lane & 16) ? 8u : 0u);
    const uint32_t bcolk = (lane & 8) ? 16u : 0u;

#pragma unroll
    for (int kk = 0; kk < 4; kk++) {
        const uint32_t ac = kk * 32 + acolk;
        const uint32_t bc = kk * 32 + bcolk;
        uint32_t ah[2][4], al[2][4], bh[4][4], bl[4][4];
#pragma unroll
        for (int mt = 0; mt < 2; mt++) {
            uint32_t off = swz((arow + mt * 16) * 128 + ac);
            LDSM4(ah[mt][0], ah[mt][1], ah[mt][2], ah[mt][3], base + OFF_AHI + off);
            LDSM4(al[mt][0], al[mt][1], al[mt][2], al[mt][3], base + OFF_ALO + off);
        }
#pragma unroll
        for (int ng = 0; ng < 4; ng++) {
            uint32_t off = swz((brow + ng * 16) * 128 + bc);
            LDSM4(bh[ng][0], bh[ng][1], bh[ng][2], bh[ng][3], base + OFF_BHI + off);
            LDSM4(bl[ng][0], bl[ng][1], bl[ng][2], bl[ng][3], base + OFF_BLO + off);
        }
#pragma unroll
        for (int mt = 0; mt < 2; mt++)
#pragma unroll
            for (int nf = 0; nf < 8; nf++) {
                const int ng = nf >> 1, h2 = nf & 1;
                MMA_BF16(acc[mt][nf], ah[mt], bh[ng][h2 * 2], bh[ng][h2 * 2 + 1]);
                MMA_BF16(acc[mt][nf], ah[mt], bl[ng][h2 * 2], bl[ng][h2 * 2 + 1]);
                MMA_BF16(acc[mt][nf], al[mt], bh[ng][h2 * 2], bh[ng][h2 * 2 + 1]);
            }
    }
}

static __device__ __forceinline__ void gemm_core(
    uint32_t sb,
    const __nv_bfloat16* Ahi, const __nv_bfloat16* Alo,
    const __nv_bfloat16* Bhi, const __nv_bfloat16* Blo,
    int m0, int n0, float acc[2][8][4])
{
    const int tid = threadIdx.x;
    const int wid = tid >> 5, lane = tid & 31;
    const int wm = wid >> 1, wn = wid & 1;

#pragma unroll
    for (int mt = 0; mt < 2; mt++)
#pragma unroll
        for (int nf = 0; nf < 8; nf++)
#pragma unroll
            for (int j = 0; j < 4; j++) acc[mt][nf][j] = 0.f;

    load_stage(sb, 0, Ahi, Alo, Bhi, Blo, m0, n0, 0, tid);
    asm volatile("cp.async.commit_group;" ::: "memory");
    load_stage(sb, 1, Ahi, Alo, Bhi, Blo, m0, n0, 64, tid);
    asm volatile("cp.async.commit_group;" ::: "memory");

    for (int s = 0; s < 16; s++) {
        asm volatile("cp.async.wait_group 1;" ::: "memory");
        __syncthreads();
        if (s + 2 < 16)
            load_stage(sb, (s + 2) % NST, Ahi, Alo, Bhi, Blo, m0, n0,
                       (s + 2) * 64, tid);
        asm volatile("cp.async.commit_group;" ::: "memory");
        compute_stage(sb + (s % NST) * STAGE, wm, wn, lane, acc);
    }
}

// ---------------------------------------------------------------------------
// QKV projection: z selects q/k/v, scatter into [B,H,S,D] fp32 scratch
// ---------------------------------------------------------------------------
__global__ __launch_bounds__(256, 1) void qkv_mma(
    const float* __restrict__ bq, const float* __restrict__ bk,
    const float* __restrict__ bv)
{
    extern __shared__ __align__(1024) char dsm[];
    const uint32_t sb = s2u(dsm);
    const int tid = threadIdx.x, wid = tid >> 5, lane = tid & 31;
    const int wm = wid >> 1, wn = wid & 1;

    const int which = blockIdx.z;
    const __nv_bfloat16* Bhi = g_whi + ((size_t)which << 20);
    const __nv_bfloat16* Blo = g_wlo + ((size_t)which << 20);
    const float* bias = (which == 0) ? bq : (which == 1) ? bk : bv;
    float* dst        = (which == 0) ? g_q : (which == 1) ? g_k : g_v;

    const int m0 = blockIdx.y * 128, n0 = blockIdx.x * 128;
    float acc[2][8][4];
    gemm_core(sb, g_xhi, g_xlo, Bhi, Blo, m0, n0, acc);

    const int qr = lane >> 2, qc = (lane & 3) * 2;
#pragma unroll
    for (int mt = 0; mt < 2; mt++) {
        const int mr0 = m0 + wm * 32 + mt * 16 + qr;
        const int mr1 = mr0 + 8;
        const int b0 = mr0 / S_, s0 = mr0 - b0 * S_;
        const int b1 = mr1 / S_, s1 = mr1 - b1 * S_;
#pragma unroll
        for (int nf = 0; nf < 8; nf++) {
            const int c = n0 + wn * 64 + nf * 8 + qc;
            const int h = c >> 6, dc = c & 63;
            const float bx = bias[c], by = bias[c + 1];
            float* p0 = dst + ((size_t)(b0 * H_ + h) * S_ + s0) * D_ + dc;
            float* p1 = dst + ((size_t)(b1 * H_ + h) * S_ + s1) * D_ + dc;
            *(float2*)p0 = make_float2(acc[mt][nf][0] + bx, acc[mt][nf][1] + by);
            *(float2*)p1 = make_float2(acc[mt][nf][2] + bx, acc[mt][nf][3] + by);
        }
    }
}

// ---------------------------------------------------------------------------
// Output projection: reads y splits, writes d_out row-major
// ---------------------------------------------------------------------------
__global__ __launch_bounds__(256, 1) void proj_mma(
    const float* __restrict__ bp, float* __restrict__ out)
{
    extern __shared__ __align__(1024) char dsm[];
    const uint32_t sb = s2u(dsm);
    const int tid = threadIdx.x, wid = tid >> 5, lane = tid & 31;
    const int wm = wid >> 1, wn = wid & 1;

    const __nv_bfloat16* Bhi = g_whi + ((size_t)3 << 20);
    const __nv_bfloat16* Blo = g_wlo + ((size_t)3 << 20);

    const int m0 = blockIdx.y * 128, n0 = blockIdx.x * 128;
    float acc[2][8][4];
    gemm_core(sb, g_yhi, g_ylo, Bhi, Blo, m0, n0, acc);

    const int qr = lane >> 2, qc = (lane & 3) * 2;
#pragma unroll
    for (int mt = 0; mt < 2; mt++) {
        const int mr0 = m0 + wm * 32 + mt * 16 + qr;
#pragma unroll
        for (int nf = 0; nf < 8; nf++) {
            const int c = n0 + wn * 64 + nf * 8 + qc;
            const float bx = bp[c], by = bp[c + 1];
            *(float2*)(out + (size_t)mr0 * C_ + c) =
                make_float2(acc[mt][nf][0] + bx, acc[mt][nf][1] + by);
            *(float2*)(out + (size_t)(mr0 + 8) * C_ + c) =
                make_float2(acc[mt][nf][2] + bx, acc[mt][nf][3] + by);
        }
    }
}

// ---------------------------------------------------------------------------
// Pre-pass: split x into bf16 hi/lo
// ---------------------------------------------------------------------------
__global__ void split_x_kernel(const float* __restrict__ x)
{
    const size_t i = ((size_t)blockIdx.x * 256 + threadIdx.x) * 4;
    float4 v = *(const float4*)(x + i);
    __nv_bfloat162 h01 = __floats2bfloat162_rn(v.x, v.y);
    __nv_bfloat162 h23 = __floats2bfloat162_rn(v.z, v.w);
    __nv_bfloat162 l01 = __floats2bfloat162_rn(v.x - __low2float(h01),
                                               v.y - __high2float(h01));
    __nv_bfloat162 l23 = __floats2bfloat162_rn(v.z - __low2float(h23),
                                               v.w - __high2float(h23));
    *(__nv_bfloat162*)(g_xhi + i)     = h01;
    *(__nv_bfloat162*)(g_xhi + i + 2) = h23;
    *(__nv_bfloat162*)(g_xlo + i)     = l01;
    *(__nv_bfloat162*)(g_xlo + i + 2) = l23;
}

// Pre-pass: transpose weights to [n][k] and split into bf16 hi/lo
__global__ void wsplit_kernel(
    const float* __restrict__ Wq, const float* __restrict__ Wk,
    const float* __restrict__ Wv, const float* __restrict__ Wp)
{
    __shared__ float t[32][33];
    const int z = blockIdx.z;
    const float* src = (z == 0) ? Wq : (z == 1) ? Wk : (z == 2) ? Wv : Wp;
    const size_t zoff = (size_t)z << 20;
    const int x0 = blockIdx.x * 32, y0 = blockIdx.y * 32;
    const int tx = threadIdx.x, ty = threadIdx.y;
#pragma unroll
    for (int i = 0; i < 32; i += 8)
        t[ty + i][tx] = src[(size_t)(y0 + ty + i) * 1024 + x0 + tx];
    __syncthreads();
#pragma unroll
    for (int i = 0; i < 32; i += 8) {
        float v = t[tx][ty + i];           // = W[y0+tx][x0+ty+i]
        __nv_bfloat16 h = __float2bfloat16(v);
        size_t o = zoff + (size_t)(x0 + ty + i) * 1024 + (y0 + tx);
        g_whi[o] = h;
        g_wlo[o] = __float2bfloat16(v - __bfloat162float(h));
    }
}

// ---------------------------------------------------------------------------
// Flash attention (fp32), epilogue emits y as bf16 hi/lo splits
// ---------------------------------------------------------------------------
__global__ __launch_bounds__(256) void attn_kernel()
{
    constexpr int LD = 64;
    __shared__ float sQ[64 * LD];
    __shared__ float sKP[64 * LD];
    __shared__ float sV[64 * LD];

    const int qt  = blockIdx.x;
    const int bh  = blockIdx.y;
    const int tid = threadIdx.x;
    const int ty = tid >> 4, tx = tid & 15;

    const float* qb = g_q + bh * (S_ * D_);
    const float* kb = g_k + bh * (S_ * D_);
    const float* vb = g_v + bh * (S_ * D_);

    const int rL = tid >> 4;
    const int d4 = (tid & 15) << 2;

#pragma unroll
    for (int it = 0; it < 4; it++) {
        int r = rL + it * 16;
        int qpos = qt * 64 + r;
        float4 val = make_float4(0.f, 0.f, 0.f, 0.f);
        if (qpos < S_) val = *(const float4*)(qb + qpos * D_ + d4);
        *(float4*)&sQ[r * LD + d4] = val;
    }

    float o[4][4];
    float m_i[4], l_i[4];
#pragma unroll
    for (int i = 0; i < 4; i++) {
        m_i[i] = -1e30f; l_i[i] = 0.f;
#pragma unroll
        for (int j = 0; j < 4; j++) o[i][j] = 0.f;
    }

    for (int kt = 0; kt <= qt; kt++) {
        __syncthreads();
#pragma unroll
        for (int it = 0; it < 4; it++) {
            int c = rL + it * 16;
            int kpos = kt * 64 + c;
            float4 kv = make_float4(0.f, 0.f, 0.f, 0.f);
            float4 vv = make_float4(0.f, 0.f, 0.f, 0.f);
            if (kpos < S_) {
                kv = *(const float4*)(kb + kpos * D_ + d4);
                vv = *(const float4*)(vb + kpos * D_ + d4);
            }
            sKP[(d4 + 0) * LD + c] = kv.x;
            sKP[(d4 + 1) * LD + c] = kv.y;
            sKP[(d4 + 2) * LD + c] = kv.z;
            sKP[(d4 + 3) * LD + c] = kv.w;
            *(float4*)&sV[c * LD + d4] = vv;
        }
        __syncthreads();

        float sc[4][4];
#pragma unroll
        for (int i = 0; i < 4; i++)
#pragma unroll
            for (int j = 0; j < 4; j++) sc[i][j] = 0.f;

#pragma unroll 8
        for (int dd = 0; dd < 64; dd++) {
            float4 kf = *(const float4*)&sKP[dd * LD + tx * 4];
            float q0 = sQ[(ty * 4 + 0) * LD + dd];
            float q1 = sQ[(ty * 4 + 1) * LD + dd];
            float q2 = sQ[(ty * 4 + 2) * LD + dd];
            float q3 = sQ[(ty * 4 + 3) * LD + dd];
            sc[0][0] = fmaf(q0, kf.x, sc[0][0]);
            sc[0][1] = fmaf(q0, kf.y, sc[0][1]);
            sc[0][2] = fmaf(q0, kf.z, sc[0][2]);
            sc[0][3] = fmaf(q0, kf.w, sc[0][3]);
            sc[1][0] = fmaf(q1, kf.x, sc[1][0]);
            sc[1][1] = fmaf(q1, kf.y, sc[1][1]);
            sc[1][2] = fmaf(q1, kf.z, sc[1][2]);
            sc[1][3] = fmaf(q1, kf.w, sc[1][3]);
            sc[2][0] = fmaf(q2, kf.x, sc[2][0]);
            sc[2][1] = fmaf(q2, kf.y, sc[2][1]);
            sc[2][2] = fmaf(q2, kf.z, sc[2][2]);
            sc[2][3] = fmaf(q2, kf.w, sc[2][3]);
            sc[3][0] = fmaf(q3, kf.x, sc[3][0]);
            sc[3][1] = fmaf(q3, kf.y, sc[3][1]);
            sc[3][2] = fmaf(q3, kf.z, sc[3][2]);
            sc[3][3] = fmaf(q3, kf.w, sc[3][3]);
        }

        const bool need_mask = (kt == qt) || ((kt + 1) * 64 > S_);
#pragma unroll
        for (int i = 0; i < 4; i++) {
            int qpos = qt * 64 + ty * 4 + i;
#pragma unroll
            for (int j = 0; j < 4; j++) {
                float v = sc[i][j] * 0.125f;
                if (need_mask) {
                    int kpos = kt * 64 + tx * 4 + j;
                    if (kpos > qpos || kpos >= S_) v = -1e30f;
                }
                sc[i][j] = v;
            }
        }

#pragma unroll
        for (int i = 0; i < 4; i++) {
            float mt = fmaxf(fmaxf(sc[i][0], sc[i][1]), fmaxf(sc[i][2], sc[i][3]));
#pragma unroll
            for (int off = 8; off > 0; off >>= 1)
                mt = fmaxf(mt, __shfl_xor_sync(0xffffffffu, mt, off));
            float mnew = fmaxf(m_i[i], mt);
            float corr = __expf(m_i[i] - mnew);
            m_i[i] = mnew;
            float rs = 0.f;
#pragma unroll
            for (int j = 0; j < 4; j++) {
                sc[i][j] = __expf(sc[i][j] - mnew);
                rs += sc[i][j];
            }
#pragma unroll
            for (int off = 8; off > 0; off >>= 1)
                rs += __shfl_xor_sync(0xffffffffu, rs, off);
            l_i[i] = l_i[i] * corr + rs;
#pragma unroll
            for (int j = 0; j < 4; j++) o[i][j] *= corr;
        }

        __syncthreads();
#pragma unroll
        for (int i = 0; i < 4; i++)
            *(float4*)&sKP[(ty * 4 + i) * LD + tx * 4] =
                make_float4(sc[i][0], sc[i][1], sc[i][2], sc[i][3]);
        __syncthreads();

#pragma unroll 8
        for (int kk = 0; kk < 64; kk++) {
            float4 vf = *(const float4*)&sV[kk * LD + tx * 4];
            float p0 = sKP[(ty * 4 + 0) * LD + kk];
            float p1 = sKP[(ty * 4 + 1) * LD + kk];
            float p2 = sKP[(ty * 4 + 2) * LD + kk];
            float p3 = sKP[(ty * 4 + 3) * LD + kk];
            o[0][0] = fmaf(p0, vf.x, o[0][0]);
            o[0][1] = fmaf(p0, vf.y, o[0][1]);
            o[0][2] = fmaf(p0, vf.z, o[0][2]);
            o[0][3] = fmaf(p0, vf.w, o[0][3]);
            o[1][0] = fmaf(p1, vf.x, o[1][0]);
            o[1][1] = fmaf(p1, vf.y, o[1][1]);
            o[1][2] = fmaf(p1, vf.z, o[1][2]);
            o[1][3] = fmaf(p1, vf.w, o[1][3]);
            o[2][0] = fmaf(p2, vf.x, o[2][0]);
            o[2][1] = fmaf(p2, vf.y, o[2][1]);
            o[2][2] = fmaf(p2, vf.z, o[2][2]);
            o[2][3] = fmaf(p2, vf.w, o[2][3]);
            o[3][0] = fmaf(p3, vf.x, o[3][0]);
            o[3][1] = fmaf(p3, vf.y, o[3][1]);
            o[3][2] = fmaf(p3, vf.z, o[3][2]);
            o[3][3] = fmaf(p3, vf.w, o[3][3]);
        }
    }

    const int h = bh & (H_ - 1);
    const int b = bh >> 4;
#pragma unroll
    for (int i = 0; i < 4; i++) {
        int qpos = qt * 64 + ty * 4 + i;
        if (qpos >= S_) continue;
        float inv = 1.f / l_i[i];
        float vx = o[i][0] * inv, vy = o[i][1] * inv;
        float vz = o[i][2] * inv, vw = o[i][3] * inv;
        __nv_bfloat162 hxy = __floats2bfloat162_rn(vx, vy);
        __nv_bfloat162 hzw = __floats2bfloat162_rn(vz, vw);
        __nv_bfloat162 lxy = __floats2bfloat162_rn(vx - __low2float(hxy),
                                                   vy - __high2float(hxy));
        __nv_bfloat162 lzw = __floats2bfloat162_rn(vz - __low2float(hzw),
                                                   vw - __high2float(hzw));
        size_t off = ((size_t)(b * S_ + qpos)) * C_ + h * D_ + tx * 4;
        *(__nv_bfloat162*)(g_yhi + off)     = hxy;
        *(__nv_bfloat162*)(g_yhi + off + 2) = hzw;
        *(__nv_bfloat162*)(g_ylo + off)     = lxy;
        *(__nv_bfloat162*)(g_ylo + off + 2) = lzw;
    }
}

// ---------------------------------------------------------------------------
extern "C" void kernel_launch(void* const* d_in, const int* in_sizes, int n_in,
                              void* d_out, int out_size)
{
    const float* x  = (const float*)d_in[0];
    const float* Wq = (const float*)d_in[1];
    const float* bq = (const float*)d_in[2];
    const float* Wk = (const float*)d_in[3];
    const float* bk = (const float*)d_in[4];
    const float* Wv = (const float*)d_in[5];
    const float* bv = (const float*)d_in[6];
    const float* Wp = (const float*)d_in[7];
    const float* bp = (const float*)d_in[8];
    float* out = (float*)d_out;

    cudaFuncSetAttribute(qkv_mma, cudaFuncAttributeMaxDynamicSharedMemorySize, GSMEM);
    cudaFuncSetAttribute(proj_mma, cudaFuncAttributeMaxDynamicSharedMemorySize, GSMEM);

    split_x_kernel<<<M_ * C_ / 1024, 256>>>(x);
    wsplit_kernel<<<dim3(32, 32, 4), dim3(32, 8)>>>(Wq, Wk, Wv, Wp);
    qkv_mma<<<dim3(8, 125, 3), 256, GSMEM>>>(bq, bk, bv);
    attn_kernel<<<dim3(8, BH_), 256>>>();
    proj_mma<<<dim3(8, 125), 256, GSMEM>>>(bp, out);
}

// round 4
// speedup vs baseline: 2.2416x; 1.2387x over previous
#include <cuda_runtime.h>
#include <cuda_bf16.h>
#include <cstdint>

namespace {
constexpr int B_ = 32, S_ = 500, C_ = 1024, H_ = 16, D_ = 64;
constexpr int BH_ = B_ * H_;   // 512
constexpr int M_  = B_ * S_;   // 16000

// GEMM smem layout: per stage [Ahi 16K][Alo 16K][Bhi 16K][Blo 16K]
constexpr int OFF_AHI = 0;
constexpr int OFF_ALO = 16384;
constexpr int OFF_BHI = 32768;
constexpr int OFF_BLO = 49152;
constexpr int STAGE   = 65536;
constexpr int NST     = 3;
constexpr int GSMEM   = STAGE * NST;   // 192KB

// Attention smem layout
constexpr int AQHI = 0;          // 64 x 128B
constexpr int AQLO = 8192;
constexpr int AKV0 = 16384;      // stage: [KHI 8K][KLO 8K][VHI 8K][VLO 8K]
constexpr int AKHI = 0, AKLO = 8192, AVHI = 16384, AVLO = 24576;
constexpr int AKV_STRIDE = 32768;
constexpr int ASMEM = AKV0 + 2 * AKV_STRIDE;  // 80KB
}

// Scratch (__device__ globals: allocation-free rule)
__device__ __align__(128) __nv_bfloat16 g_qhi[(size_t)BH_ * S_ * D_];
__device__ __align__(128) __nv_bfloat16 g_qlo[(size_t)BH_ * S_ * D_];
__device__ __align__(128) __nv_bfloat16 g_khi[(size_t)BH_ * S_ * D_];
__device__ __align__(128) __nv_bfloat16 g_klo[(size_t)BH_ * S_ * D_];
__device__ __align__(128) __nv_bfloat16 g_vhi[(size_t)BH_ * S_ * D_];
__device__ __align__(128) __nv_bfloat16 g_vlo[(size_t)BH_ * S_ * D_];
__device__ __align__(128) __nv_bfloat16 g_xhi[(size_t)M_ * C_];
__device__ __align__(128) __nv_bfloat16 g_xlo[(size_t)M_ * C_];
__device__ __align__(128) __nv_bfloat16 g_yhi[(size_t)M_ * C_];
__device__ __align__(128) __nv_bfloat16 g_ylo[(size_t)M_ * C_];
__device__ __align__(128) __nv_bfloat16 g_whi[4u * 1024u * 1024u];  // [z][n][k]
__device__ __align__(128) __nv_bfloat16 g_wlo[4u * 1024u * 1024u];

// ---------------------------------------------------------------------------
// helpers
// ---------------------------------------------------------------------------
static __device__ __forceinline__ uint32_t s2u(const void* p) {
    uint32_t a;
    asm("{ .reg .u64 t; cvta.to.shared.u64 t, %1; cvt.u32.u64 %0, t; }"
        : "=r"(a) : "l"(p));
    return a;
}
static __device__ __forceinline__ uint32_t swz(uint32_t o) {
    return o ^ ((o >> 3) & 0x70u);
}
static __device__ __forceinline__ void cpa16(uint32_t s, const void* g) {
    asm volatile("cp.async.cg.shared.global [%0], [%1], 16;" :: "r"(s), "l"(g));
}
static __device__ __forceinline__ void cpa16z(uint32_t s, const void* g, uint32_t sz) {
    asm volatile("cp.async.cg.shared.global [%0], [%1], 16, %2;"
                 :: "r"(s), "l"(g), "r"(sz));
}
static __device__ __forceinline__ uint32_t packbf2(float a, float b) {
    __nv_bfloat162 h = __floats2bfloat162_rn(a, b);
    return *(uint32_t*)&h;
}

#define LDSM4(r0, r1, r2, r3, a) \
    asm volatile("ldmatrix.sync.aligned.m8n8.x4.shared.b16 {%0,%1,%2,%3}, [%4];" \
                 : "=r"(r0), "=r"(r1), "=r"(r2), "=r"(r3) : "r"(a))
#define LDSM4T(r0, r1, r2, r3, a) \
    asm volatile("ldmatrix.sync.aligned.m8n8.x4.trans.shared.b16 {%0,%1,%2,%3}, [%4];" \
                 : "=r"(r0), "=r"(r1), "=r"(r2), "=r"(r3) : "r"(a))

#define MMA_BF16(d, a, b0, b1) \
    asm volatile( \
        "mma.sync.aligned.m16n8k16.row.col.f32.bf16.bf16.f32 " \
        "{%0,%1,%2,%3}, {%4,%5,%6,%7}, {%8,%9}, {%0,%1,%2,%3};" \
        : "+f"((d)[0]), "+f"((d)[1]), "+f"((d)[2]), "+f"((d)[3]) \
        : "r"((a)[0]), "r"((a)[1]), "r"((a)[2]), "r"((a)[3]), \
          "r"(b0), "r"(b1))

// ---------------------------------------------------------------------------
// GEMM core: C[128x128] = A[128x1024] * B^T (B stored [n][k]), bf16x3 splits
// ---------------------------------------------------------------------------
static __device__ __forceinline__ void load_stage(
    uint32_t sb, int buf,
    const __nv_bfloat16* __restrict__ Ahi, const __nv_bfloat16* __restrict__ Alo,
    const __nv_bfloat16* __restrict__ Bhi, const __nv_bfloat16* __restrict__ Blo,
    int m0, int n0, int k0, int tid)
{
    const int r = tid >> 1;
    const int half = tid & 1;
    const uint32_t base = sb + buf * STAGE;
    const size_t ga = (size_t)(m0 + r) * C_ + k0 + half * 32;
    const size_t gb = (size_t)(n0 + r) * C_ + k0 + half * 32;
#pragma unroll
    for (int i = 0; i < 4; i++) {
        uint32_t so = swz((uint32_t)(r * 128 + half * 64 + i * 16));
        cpa16(base + OFF_AHI + so, Ahi + ga + i * 8);
        cpa16(base + OFF_ALO + so, Alo + ga + i * 8);
        cpa16(base + OFF_BHI + so, Bhi + gb + i * 8);
        cpa16(base + OFF_BLO + so, Blo + gb + i * 8);
    }
}

static __device__ __forceinline__ void compute_stage(
    uint32_t base, int wm, int wn, int lane, float acc[2][8][4])
{
    const uint32_t arow  = wm * 32 + (lane & 15);
    const uint32_t acolk = (lane & 16) ? 16u : 0u;
    const uint32_t brow  = wn * 64 + (lane & 7) + ((lane & 16) ? 8u : 0u);
    const uint32_t bcolk = (lane & 8) ? 16u : 0u;

#pragma unroll
    for (int kk = 0; kk < 4; kk++) {
        const uint32_t ac = kk * 32 + acolk;
        const uint32_t bc = kk * 32 + bcolk;
        uint32_t ah[2][4], al[2][4], bh[4][4], bl[4][4];
#pragma unroll
        for (int mt = 0; mt < 2; mt++) {
            uint32_t off = swz((arow + mt * 16) * 128 + ac);
            LDSM4(ah[mt][0], ah[mt][1], ah[mt][2], ah[mt][3], base + OFF_AHI + off);
            LDSM4(al[mt][0], al[mt][1], al[mt][2], al[mt][3], base + OFF_ALO + off);
        }
#pragma unroll
        for (int ng = 0; ng < 4; ng++) {
            uint32_t off = swz((brow + ng * 16) * 128 + bc);
            LDSM4(bh[ng][0], bh[ng][1], bh[ng][2], bh[ng][3], base + OFF_BHI + off);
            LDSM4(bl[ng][0], bl[ng][1], bl[ng][2], bl[ng][3], base + OFF_BLO + off);
        }
#pragma unroll
        for (int mt = 0; mt < 2; mt++)
#pragma unroll
            for (int nf = 0; nf < 8; nf++) {
                const int ng = nf >> 1, h2 = nf & 1;
                MMA_BF16(acc[mt][nf], ah[mt], bh[ng][h2 * 2], bh[ng][h2 * 2 + 1]);
                MMA_BF16(acc[mt][nf], ah[mt], bl[ng][h2 * 2], bl[ng][h2 * 2 + 1]);
                MMA_BF16(acc[mt][nf], al[mt], bh[ng][h2 * 2], bh[ng][h2 * 2 + 1]);
            }
    }
}

static __device__ __forceinline__ void gemm_core(
    uint32_t sb,
    const __nv_bfloat16* Ahi, const __nv_bfloat16* Alo,
    const __nv_bfloat16* Bhi, const __nv_bfloat16* Blo,
    int m0, int n0, float acc[2][8][4])
{
    const int tid = threadIdx.x;
    const int wid = tid >> 5, lane = tid & 31;
    const int wm = wid >> 1, wn = wid & 1;

#pragma unroll
    for (int mt = 0; mt < 2; mt++)
#pragma unroll
        for (int nf = 0; nf < 8; nf++)
#pragma unroll
            for (int j = 0; j < 4; j++) acc[mt][nf][j] = 0.f;

    load_stage(sb, 0, Ahi, Alo, Bhi, Blo, m0, n0, 0, tid);
    asm volatile("cp.async.commit_group;" ::: "memory");
    load_stage(sb, 1, Ahi, Alo, Bhi, Blo, m0, n0, 64, tid);
    asm volatile("cp.async.commit_group;" ::: "memory");

    for (int s = 0; s < 16; s++) {
        asm volatile("cp.async.wait_group 1;" ::: "memory");
        __syncthreads();
        if (s + 2 < 16)
            load_stage(sb, (s + 2) % NST, Ahi, Alo, Bhi, Blo, m0, n0,
                       (s + 2) * 64, tid);
        asm volatile("cp.async.commit_group;" ::: "memory");
        compute_stage(sb + (s % NST) * STAGE, wm, wn, lane, acc);
    }
}

// ---------------------------------------------------------------------------
// QKV projection: epilogue emits bf16 hi/lo into [B,H,S,D]; Q scaled by 1/8
// ---------------------------------------------------------------------------
__global__ __launch_bounds__(256, 1) void qkv_mma(
    const float* __restrict__ bq, const float* __restrict__ bk,
    const float* __restrict__ bv)
{
    extern __shared__ __align__(1024) char dsm[];
    const uint32_t sb = s2u(dsm);
    const int tid = threadIdx.x, wid = tid >> 5, lane = tid & 31;
    const int wm = wid >> 1, wn = wid & 1;

    const int which = blockIdx.z;
    const __nv_bfloat16* Bhi = g_whi + ((size_t)which << 20);
    const __nv_bfloat16* Blo = g_wlo + ((size_t)which << 20);
    const float* bias = (which == 0) ? bq : (which == 1) ? bk : bv;
    __nv_bfloat16* dhi = (which == 0) ? g_qhi : (which == 1) ? g_khi : g_vhi;
    __nv_bfloat16* dlo = (which == 0) ? g_qlo : (which == 1) ? g_klo : g_vlo;
    const float scale = (which == 0) ? 0.125f : 1.0f;

    const int m0 = blockIdx.y * 128, n0 = blockIdx.x * 128;
    float acc[2][8][4];
    gemm_core(sb, g_xhi, g_xlo, Bhi, Blo, m0, n0, acc);

    const int qr = lane >> 2, qc = (lane & 3) * 2;
#pragma unroll
    for (int mt = 0; mt < 2; mt++) {
        const int mr0 = m0 + wm * 32 + mt * 16 + qr;
        const int mr1 = mr0 + 8;
        const int b0 = mr0 / S_, s0 = mr0 - b0 * S_;
        const int b1 = mr1 / S_, s1 = mr1 - b1 * S_;
#pragma unroll
        for (int nf = 0; nf < 8; nf++) {
            const int c = n0 + wn * 64 + nf * 8 + qc;
            const int h = c >> 6, dc = c & 63;
            const float bx = bias[c], by = bias[c + 1];
            float v0 = (acc[mt][nf][0] + bx) * scale;
            float v1 = (acc[mt][nf][1] + by) * scale;
            float v2 = (acc[mt][nf][2] + bx) * scale;
            float v3 = (acc[mt][nf][3] + by) * scale;
            size_t i0 = ((size_t)(b0 * H_ + h) * S_ + s0) * D_ + dc;
            size_t i1 = ((size_t)(b1 * H_ + h) * S_ + s1) * D_ + dc;
            __nv_bfloat162 h0 = __floats2bfloat162_rn(v0, v1);
            __nv_bfloat162 h1 = __floats2bfloat162_rn(v2, v3);
            __nv_bfloat162 l0 = __floats2bfloat162_rn(v0 - __low2float(h0),
                                                      v1 - __high2float(h0));
            __nv_bfloat162 l1 = __floats2bfloat162_rn(v2 - __low2float(h1),
                                                      v3 - __high2float(h1));
            *(__nv_bfloat162*)(dhi + i0) = h0;
            *(__nv_bfloat162*)(dhi + i1) = h1;
            *(__nv_bfloat162*)(dlo + i0) = l0;
            *(__nv_bfloat162*)(dlo + i1) = l1;
        }
    }
}

// ---------------------------------------------------------------------------
// Output projection: reads y splits, writes d_out row-major
// ---------------------------------------------------------------------------
__global__ __launch_bounds__(256, 1) void proj_mma(
    const float* __restrict__ bp, float* __restrict__ out)
{
    extern __shared__ __align__(1024) char dsm[];
    const uint32_t sb = s2u(dsm);
    const int tid = threadIdx.x, wid = tid >> 5, lane = tid & 31;
    const int wm = wid >> 1, wn = wid & 1;

    const __nv_bfloat16* Bhi = g_whi + ((size_t)3 << 20);
    const __nv_bfloat16* Blo = g_wlo + ((size_t)3 << 20);

    const int m0 = blockIdx.y * 128, n0 = blockIdx.x * 128;
    float acc[2][8][4];
    gemm_core(sb, g_yhi, g_ylo, Bhi, Blo, m0, n0, acc);

    const int qr = lane >> 2, qc = (lane & 3) * 2;
#pragma unroll
    for (int mt = 0; mt < 2; mt++) {
        const int mr0 = m0 + wm * 32 + mt * 16 + qr;
#pragma unroll
        for (int nf = 0; nf < 8; nf++) {
            const int c = n0 + wn * 64 + nf * 8 + qc;
            const float bx = bp[c], by = bp[c + 1];
            *(float2*)(out + (size_t)mr0 * C_ + c) =
                make_float2(acc[mt][nf][0] + bx, acc[mt][nf][1] + by);
            *(float2*)(out + (size_t)(mr0 + 8) * C_ + c) =
                make_float2(acc[mt][nf][2] + bx, acc[mt][nf][3] + by);
        }
    }
}

// ---------------------------------------------------------------------------
// Pre-pass: split x / transpose+split weights
// ---------------------------------------------------------------------------
__global__ void split_x_kernel(const float* __restrict__ x)
{
    const size_t i = ((size_t)blockIdx.x * 256 + threadIdx.x) * 4;
    float4 v = *(const float4*)(x + i);
    __nv_bfloat162 h01 = __floats2bfloat162_rn(v.x, v.y);
    __nv_bfloat162 h23 = __floats2bfloat162_rn(v.z, v.w);
    __nv_bfloat162 l01 = __floats2bfloat162_rn(v.x - __low2float(h01),
                                               v.y - __high2float(h01));
    __nv_bfloat162 l23 = __floats2bfloat162_rn(v.z - __low2float(h23),
                                               v.w - __high2float(h23));
    *(__nv_bfloat162*)(g_xhi + i)     = h01;
    *(__nv_bfloat162*)(g_xhi + i + 2) = h23;
    *(__nv_bfloat162*)(g_xlo + i)     = l01;
    *(__nv_bfloat162*)(g_xlo + i + 2) = l23;
}

__global__ void wsplit_kernel(
    const float* __restrict__ Wq, const float* __restrict__ Wk,
    const float* __restrict__ Wv, const float* __restrict__ Wp)
{
    __shared__ float t[32][33];
    const int z = blockIdx.z;
    const float* src = (z == 0) ? Wq : (z == 1) ? Wk : (z == 2) ? Wv : Wp;
    const size_t zoff = (size_t)z << 20;
    const int x0 = blockIdx.x * 32, y0 = blockIdx.y * 32;
    const int tx = threadIdx.x, ty = threadIdx.y;
#pragma unroll
    for (int i = 0; i < 32; i += 8)
        t[ty + i][tx] = src[(size_t)(y0 + ty + i) * 1024 + x0 + tx];
    __syncthreads();
#pragma unroll
    for (int i = 0; i < 32; i += 8) {
        float v = t[tx][ty + i];
        __nv_bfloat16 h = __float2bfloat16(v);
        size_t o = zoff + (size_t)(x0 + ty + i) * 1024 + (y0 + tx);
        g_whi[o] = h;
        g_wlo[o] = __float2bfloat16(v - __bfloat162float(h));
    }
}

// ---------------------------------------------------------------------------
// Flash attention on tensor cores: 4 warps, 64 q-rows, bf16x3 both GEMMs
// ---------------------------------------------------------------------------
static __device__ __forceinline__ void attn_load_kv(
    uint32_t sb, int buf, size_t boff, int kt, int tid)
{
    const int r = tid >> 1;
    const int cb = (tid & 1) * 4;
    const int kpos = kt * 64 + r;
    const uint32_t sz = (kpos < S_) ? 16u : 0u;
    const int kc = (kpos < S_) ? kpos : (S_ - 1);
    const uint32_t base = sb + AKV0 + buf * AKV_STRIDE;
    const size_t g = boff + (size_t)kc * D_;
#pragma unroll
    for (int i = 0; i < 4; i++) {
        const int chunk = cb + i;
        const uint32_t sw = swz((uint32_t)(r * 128 + chunk * 16));
        cpa16z(base + AKHI + sw, g_khi + g + chunk * 8, sz);
        cpa16z(base + AKLO + sw, g_klo + g + chunk * 8, sz);
        cpa16z(base + AVHI + sw, g_vhi + g + chunk * 8, sz);
        cpa16z(base + AVLO + sw, g_vlo + g + chunk * 8, sz);
    }
}

__global__ __launch_bounds__(128) void attn_mma()
{
    extern __shared__ __align__(1024) char asm_[];
    const uint32_t sb = s2u(asm_);
    const int tid = threadIdx.x, wid = tid >> 5, lane = tid & 31;
    const int qt = blockIdx.x, bh = blockIdx.y;
    const size_t boff = (size_t)bh * (S_ * D_);

    // ---- load Q tile (hi/lo) into smem, zero-padded ----
    {
        const int r = tid >> 1;
        const int cb = (tid & 1) * 4;
        const int qpos = qt * 64 + r;
        const bool ok = qpos < S_;
        const size_t g = boff + (size_t)(ok ? qpos : 0) * D_;
#pragma unroll
        for (int i = 0; i < 4; i++) {
            const int chunk = cb + i;
            const uint32_t sw = swz((uint32_t)(r * 128 + chunk * 16));
            float4 vh = make_float4(0, 0, 0, 0), vl = vh;
            if (ok) {
                vh = *(const float4*)(g_qhi + g + chunk * 8);
                vl = *(const float4*)(g_qlo + g + chunk * 8);
            }
            *(float4*)(asm_ + AQHI + sw) = vh;
            *(float4*)(asm_ + AQLO + sw) = vl;
        }
    }
    __syncthreads();

    // ---- Q fragments (register-resident across kt loop) ----
    uint32_t qfh[4][4], qfl[4][4];
    {
        const uint32_t arow = wid * 16 + (lane & 15);
        const uint32_t ack  = (lane & 16) ? 16u : 0u;
#pragma unroll
        for (int kk = 0; kk < 4; kk++) {
            uint32_t off = swz(arow * 128 + kk * 32 + ack);
            LDSM4(qfh[kk][0], qfh[kk][1], qfh[kk][2], qfh[kk][3], sb + AQHI + off);
            LDSM4(qfl[kk][0], qfl[kk][1], qfl[kk][2], qfl[kk][3], sb + AQLO + off);
        }
    }

    float o[8][4];
#pragma unroll
    for (int dn = 0; dn < 8; dn++)
#pragma unroll
        for (int j = 0; j < 4; j++) o[dn][j] = 0.f;
    float m0v = -1e30f, m1v = -1e30f, l0v = 0.f, l1v = 0.f;

    const int row0 = qt * 64 + wid * 16 + (lane >> 2);
    const int row1 = row0 + 8;

    attn_load_kv(sb, 0, boff, 0, tid);
    asm volatile("cp.async.commit_group;" ::: "memory");

    const uint32_t brow = (lane & 7) + ((lane & 16) ? 8u : 0u);
    const uint32_t bck  = (lane & 8) ? 16u : 0u;
    const uint32_t vrow = (lane & 7) + ((lane & 8) ? 8u : 0u);
    const uint32_t vck  = (lane & 16) ? 16u : 0u;

    for (int kt = 0; kt <= qt; kt++) {
        const int buf = kt & 1;
        __syncthreads();   // all warps done with buf^1 from iteration kt-1
        if (kt + 1 <= qt) {
            attn_load_kv(sb, buf ^ 1, boff, kt + 1, tid);
            asm volatile("cp.async.commit_group;" ::: "memory");
            asm volatile("cp.async.wait_group 1;" ::: "memory");
        } else {
            asm volatile("cp.async.wait_group 0;" ::: "memory");
        }
        __syncthreads();

        const uint32_t kvb = sb + AKV0 + buf * AKV_STRIDE;

        // ---- S = Q @ K^T (bf16x3) ----
        float sc[8][4];
#pragma unroll
        for (int j = 0; j < 8; j++)
#pragma unroll
            for (int q = 0; q < 4; q++) sc[j][q] = 0.f;

#pragma unroll
        for (int kk = 0; kk < 4; kk++) {
#pragma unroll
            for (int j2 = 0; j2 < 4; j2++) {
                uint32_t off = swz((j2 * 16 + brow) * 128 + kk * 32 + bck);
                uint32_t kh[4], kl[4];
                LDSM4(kh[0], kh[1], kh[2], kh[3], kvb + AKHI + off);
                LDSM4(kl[0], kl[1], kl[2], kl[3], kvb + AKLO + off);
                MMA_BF16(sc[2 * j2],     qfh[kk], kh[0], kh[1]);
                MMA_BF16(sc[2 * j2],     qfh[kk], kl[0], kl[1]);
                MMA_BF16(sc[2 * j2],     qfl[kk], kh[0], kh[1]);
                MMA_BF16(sc[2 * j2 + 1], qfh[kk], kh[2], kh[3]);
                MMA_BF16(sc[2 * j2 + 1], qfh[kk], kl[2], kl[3]);
                MMA_BF16(sc[2 * j2 + 1], qfl[kk], kh[2], kh[3]);
            }
        }

        // ---- mask (scale already folded into Q) ----
        if ((kt == qt) || ((kt + 1) * 64 > S_)) {
            const int cb = kt * 64 + (lane & 3) * 2;
#pragma unroll
            for (int j = 0; j < 8; j++) {
                const int c0 = cb + j * 8, c1 = c0 + 1;
                if (c0 > row0 || c0 >= S_) sc[j][0] = -1e30f;
                if (c1 > row0 || c1 >= S_) sc[j][1] = -1e30f;
                if (c0 > row1 || c0 >= S_) sc[j][2] = -1e30f;
                if (c1 > row1 || c1 >= S_) sc[j][3] = -1e30f;
            }
        }

        // ---- online softmax ----
        float mt0 = -1e30f, mt1 = -1e30f;
#pragma unroll
        for (int j = 0; j < 8; j++) {
            mt0 = fmaxf(mt0, fmaxf(sc[j][0], sc[j][1]));
            mt1 = fmaxf(mt1, fmaxf(sc[j][2], sc[j][3]));
        }
        mt0 = fmaxf(mt0, __shfl_xor_sync(0xffffffffu, mt0, 1));
        mt0 = fmaxf(mt0, __shfl_xor_sync(0xffffffffu, mt0, 2));
        mt1 = fmaxf(mt1, __shfl_xor_sync(0xffffffffu, mt1, 1));
        mt1 = fmaxf(mt1, __shfl_xor_sync(0xffffffffu, mt1, 2));
        const float mn0 = fmaxf(m0v, mt0), mn1 = fmaxf(m1v, mt1);
        const float cr0 = __expf(m0v - mn0), cr1 = __expf(m1v - mn1);
        m0v = mn0; m1v = mn1;

        uint32_t ph[8][2], pl[8][2];
        float rs0 = 0.f, rs1 = 0.f;
#pragma unroll
        for (int j = 0; j < 8; j++) {
            float p0 = __expf(sc[j][0] - mn0);
            float p1 = __expf(sc[j][1] - mn0);
            float p2 = __expf(sc[j][2] - mn1);
            float p3 = __expf(sc[j][3] - mn1);
            rs0 += p0 + p1; rs1 += p2 + p3;
            __nv_bfloat162 h0 = __floats2bfloat162_rn(p0, p1);
            __nv_bfloat162 h1 = __floats2bfloat162_rn(p2, p3);
            ph[j][0] = *(uint32_t*)&h0;
            ph[j][1] = *(uint32_t*)&h1;
            pl[j][0] = packbf2(p0 - __low2float(h0), p1 - __high2float(h0));
            pl[j][1] = packbf2(p2 - __low2float(h1), p3 - __high2float(h1));
        }
        rs0 += __shfl_xor_sync(0xffffffffu, rs0, 1);
        rs0 += __shfl_xor_sync(0xffffffffu, rs0, 2);
        rs1 += __shfl_xor_sync(0xffffffffu, rs1, 1);
        rs1 += __shfl_xor_sync(0xffffffffu, rs1, 2);
        l0v = l0v * cr0 + rs0;
        l1v = l1v * cr1 + rs1;
#pragma unroll
        for (int dn = 0; dn < 8; dn++) {
            o[dn][0] *= cr0; o[dn][1] *= cr0;
            o[dn][2] *= cr1; o[dn][3] *= cr1;
        }

        // ---- O += P @ V (bf16x3), V via ldmatrix.trans ----
#pragma unroll
        for (int kk = 0; kk < 4; kk++) {
            uint32_t ah[4] = {ph[2 * kk][0], ph[2 * kk][1],
                              ph[2 * kk + 1][0], ph[2 * kk + 1][1]};
            uint32_t al[4] = {pl[2 * kk][0], pl[2 * kk][1],
                              pl[2 * kk + 1][0], pl[2 * kk + 1][1]};
#pragma unroll
            for (int dj2 = 0; dj2 < 4; dj2++) {
                uint32_t off = swz((kk * 16 + vrow) * 128 + dj2 * 32 + vck);
                uint32_t vh[4], vl[4];
                LDSM4T(vh[0], vh[1], vh[2], vh[3], kvb + AVHI + off);
                LDSM4T(vl[0], vl[1], vl[2], vl[3], kvb + AVLO + off);
                MMA_BF16(o[2 * dj2],     ah, vh[0], vh[1]);
                MMA_BF16(o[2 * dj2],     ah, vl[0], vl[1]);
                MMA_BF16(o[2 * dj2],     al, vh[0], vh[1]);
                MMA_BF16(o[2 * dj2 + 1], ah, vh[2], vh[3]);
                MMA_BF16(o[2 * dj2 + 1], ah, vl[2], vl[3]);
                MMA_BF16(o[2 * dj2 + 1], al, vh[2], vh[3]);
            }
        }
    }

    // ---- epilogue: normalize, split to bf16 hi/lo, write y [M][C] ----
    const int h = bh & (H_ - 1);
    const int b = bh >> 4;
    const float inv0 = 1.f / l0v, inv1 = 1.f / l1v;
    const int dc = (lane & 3) * 2;
#pragma unroll
    for (int dn = 0; dn < 8; dn++) {
        const int d = h * D_ + dn * 8 + dc;
        if (row0 < S_) {
            float v0 = o[dn][0] * inv0, v1 = o[dn][1] * inv0;
            __nv_bfloat162 hh = __floats2bfloat162_rn(v0, v1);
            __nv_bfloat162 ll = __floats2bfloat162_rn(v0 - __low2float(hh),
                                                      v1 - __high2float(hh));
            size_t i0 = (size_t)(b * S_ + row0) * C_ + d;
            *(__nv_bfloat162*)(g_yhi + i0) = hh;
            *(__nv_bfloat162*)(g_ylo + i0) = ll;
        }
        if (row1 < S_) {
            float v2 = o[dn][2] * inv1, v3 = o[dn][3] * inv1;
            __nv_bfloat162 hh = __floats2bfloat162_rn(v2, v3);
            __nv_bfloat162 ll = __floats2bfloat162_rn(v2 - __low2float(hh),
                                                      v3 - __high2float(hh));
            size_t i1 = (size_t)(b * S_ + row1) * C_ + d;
            *(__nv_bfloat162*)(g_yhi + i1) = hh;
            *(__nv_bfloat162*)(g_ylo + i1) = ll;
        }
    }
}

// ---------------------------------------------------------------------------
extern "C" void kernel_launch(void* const* d_in, const int* in_sizes, int n_in,
                              void* d_out, int out_size)
{
    const float* x  = (const float*)d_in[0];
    const float* Wq = (const float*)d_in[1];
    const float* bq = (const float*)d_in[2];
    const float* Wk = (const float*)d_in[3];
    const float* bk = (const float*)d_in[4];
    const float* Wv = (const float*)d_in[5];
    const float* bv = (const float*)d_in[6];
    const float* Wp = (const float*)d_in[7];
    const float* bp = (const float*)d_in[8];
    float* out = (float*)d_out;

    cudaFuncSetAttribute(qkv_mma, cudaFuncAttributeMaxDynamicSharedMemorySize, GSMEM);
    cudaFuncSetAttribute(proj_mma, cudaFuncAttributeMaxDynamicSharedMemorySize, GSMEM);
    cudaFuncSetAttribute(attn_mma, cudaFuncAttributeMaxDynamicSharedMemorySize, ASMEM);

    split_x_kernel<<<M_ * C_ / 1024, 256>>>(x);
    wsplit_kernel<<<dim3(32, 32, 4), dim3(32, 8)>>>(Wq, Wk, Wv, Wp);
    qkv_mma<<<dim3(8, 125, 3), 256, GSMEM>>>(bq, bk, bv);
    attn_mma<<<dim3(8, BH_), 128, ASMEM>>>();
    proj_mma<<<dim3(8, 125), 256, GSMEM>>>(bp, out);
}